// round 11
// baseline (speedup 1.0000x reference)
#include <cuda_runtime.h>
#include <math.h>

#define D4    64            // 256 dims = 64 float4
#define C     64
#define MAXNQ 4096
#define MAXNS 8192
#define QT    32            // queries per tile
#define MB    64            // members per staged chunk
#define MAXTILES (MAXNQ/QT + C)   // 192
#define NEG  (-3.0e38f)
#define NH   48             // prep CTAs (co-resident -> grid barrier is safe)
#define ZC   32             // kCent member splits
#define SMEM_MAIN ((QT*D4 + MB*D4) * 16)   // 96 KB dynamic

// Scratch (device globals; fully rewritten every call -> replay-safe).
__device__ float g_cent[C * 256];
__device__ float g_ssum[C];
__device__ int   g_counts[C];
__device__ int   g_start[C + 1];
__device__ int   g_cidx[MAXNS];
__device__ int   g_qidx[MAXNQ];
__device__ int   g_tc[MAXTILES], g_toff[MAXTILES], g_tcnt[MAXTILES];
__device__ int   g_ntiles;
__device__ int   g_phT[C][NH];    // transposed partial hists (support)
__device__ int   g_pqhT[C][NH];   // transposed partial hists (queries)
__device__ int   g_off[C], g_qoff[C];     // scatter cursors
__device__ unsigned g_tick;       // monotonic ticket counter (never reset)

__device__ __forceinline__ float warp_sum(float v) {
#pragma unroll
    for (int o = 16; o; o >>= 1) v += __shfl_xor_sync(0xffffffffu, v, o);
    return v;
}

// Packed dual-FMA: d.lo += a.lo*b.lo ; d.hi += a.hi*b.hi   (Blackwell f32x2)
__device__ __forceinline__ void fma2(unsigned long long& d,
                                     unsigned long long a, unsigned long long b) {
    asm("fma.rn.f32x2 %0, %1, %2, %0;" : "+l"(d) : "l"(a), "l"(b));
}
__device__ __forceinline__ float hsum2(unsigned long long v) {
    float lo, hi;
    asm("mov.b64 {%0, %1}, %2;" : "=f"(lo), "=f"(hi) : "l"(v));
    return lo + hi;
}

// Monotonic-ticket grid barrier for NH co-resident CTAs. Correct across
// graph replays: every launch issues exactly 2*NH arrivals, episodes are
// globally ordered, targets are consecutive multiples of NH.
__device__ __forceinline__ void grid_bar() {
    __syncthreads();
    if (threadIdx.x == 0) {
        __threadfence();
        unsigned t = atomicAdd(&g_tick, 1u);
        unsigned target = (t / NH + 1u) * NH;
        while (*(volatile unsigned*)&g_tick < target) { }
        __threadfence();
    }
    __syncthreads();
}

// ---------------------------------------------------------------------------
// Kernel 1 (kPrep): 48 CTAs, fused hist -> schedule -> scatter via grid
// barriers. Also zeroes g_cent / g_ssum / d_out.
// ---------------------------------------------------------------------------
__global__ void __launch_bounds__(256)
kPrep(const int* __restrict__ ys, const int* __restrict__ yq,
      int Nq, int Ns, float* __restrict__ out) {
    __shared__ int h[8][C], hq[8][C];
    __shared__ int cnt[C], qcnt[C];
    int tid = threadIdx.x, w = tid >> 5;
    int cta = blockIdx.x;

    // Phase A: per-CTA histograms + zero chores
    for (int i = tid; i < 8 * C; i += 256) { (&h[0][0])[i] = 0; (&hq[0][0])[i] = 0; }
    __syncthreads();
    int s0 = (Ns * cta) / NH, s1 = (Ns * (cta + 1)) / NH;
    for (int j = s0 + tid; j < s1; j += 256) atomicAdd(&h[w][ys[j]], 1);
    int q0 = (Nq * cta) / NH, q1 = (Nq * (cta + 1)) / NH;
    for (int i = q0 + tid; i < q1; i += 256) atomicAdd(&hq[w][yq[i]], 1);
    __syncthreads();
    if (tid < C) {
        int s = 0;
#pragma unroll
        for (int r = 0; r < 8; r++) s += h[r][tid];
        g_phT[tid][cta] = s;
    } else if (tid < 2 * C) {
        int c = tid - C, s = 0;
#pragma unroll
        for (int r = 0; r < 8; r++) s += hq[r][c];
        g_pqhT[c][cta] = s;
    }
    for (int i = cta * 256 + tid; i < C * 256; i += NH * 256) g_cent[i] = 0.0f;
    if (cta == 1 && tid < C) g_ssum[tid] = 0.0f;
    if (cta == 2 && tid == 0) out[0] = 0.0f;

    grid_bar();

    // Phase B: CTA 0 reduces partials (contiguous rows) + builds schedule
    if (cta == 0) {
        if (tid < C) {
            int s = 0;
#pragma unroll 8
            for (int r = 0; r < NH; r++) s += g_phT[tid][r];
            cnt[tid] = s;
        } else if (tid < 2 * C) {
            int c = tid - C, s = 0;
#pragma unroll 8
            for (int r = 0; r < NH; r++) s += g_pqhT[c][r];
            qcnt[c] = s;
        }
        __syncthreads();
        if (tid == 0) {
            int acc = 0, qacc = 0, nt = 0;
            for (int c = 0; c < C; c++) {
                g_counts[c] = cnt[c]; g_start[c] = acc; g_off[c] = acc; acc += cnt[c];
                g_qoff[c] = qacc;
                for (int t = 0; t < qcnt[c]; t += QT) {
                    g_tc[nt] = c; g_toff[nt] = qacc + t;
                    g_tcnt[nt] = min(QT, qcnt[c] - t); nt++;
                }
                qacc += qcnt[c];
            }
            g_start[C] = acc; g_ntiles = nt;
        }
    }

    grid_bar();

    // Phase C: scatter via global atomic cursors (64 L2 addresses)
    for (int j = s0 + tid; j < s1; j += 256)
        g_cidx[atomicAdd(&g_off[ys[j]], 1)] = j;
    for (int i = q0 + tid; i < q1; i += 256)
        g_qidx[atomicAdd(&g_qoff[yq[i]], 1)] = i;
}

// ---------------------------------------------------------------------------
// Kernel 2 (kCent): partial centroids + partial sq-norm sums.
// Grid (C, 2, ZC): y = dim half, z = member 1/ZC slice. 4096 CTAs -> high
// MLP for the scattered row gather. atomicAdd into zeroed g_cent / g_ssum.
// ---------------------------------------------------------------------------
__global__ void kCent(const float* __restrict__ xs) {
    int c = blockIdx.x, tid = threadIdx.x;
    int dim = blockIdx.y * 128 + tid;
    int s0 = g_start[c], s1 = g_start[c + 1];
    int Mc = s1 - s0;
    int b0 = s0 + (Mc * (int)blockIdx.z) / ZC;
    int b1 = s0 + (Mc * ((int)blockIdx.z + 1)) / ZC;
    float acc = 0.0f, acc2 = 0.0f;
    int m = b0;
    for (; m + 3 < b1; m += 4) {
        float v0 = xs[(size_t)g_cidx[m]   * 256 + dim];
        float v1 = xs[(size_t)g_cidx[m+1] * 256 + dim];
        float v2 = xs[(size_t)g_cidx[m+2] * 256 + dim];
        float v3 = xs[(size_t)g_cidx[m+3] * 256 + dim];
        acc  += (v0 + v1) + (v2 + v3);
        acc2 += (v0*v0 + v1*v1) + (v2*v2 + v3*v3);
    }
    for (; m < b1; m++) {
        float v = xs[(size_t)g_cidx[m] * 256 + dim];
        acc += v; acc2 += v * v;
    }
    if (b0 < b1) atomicAdd(&g_cent[c * 256 + dim], acc);

    __shared__ float sred[128];
    sred[tid] = acc2; __syncthreads();
    for (int s = 64; s; s >>= 1) { if (tid < s) sred[tid] += sred[tid + s]; __syncthreads(); }
    if (tid == 0 && blockIdx.y == 0 && sred[0] != 0.0f) atomicAdd(&g_ssum[c], sred[0]);
    if (tid == 1 && blockIdx.y == 1 && sred[0] != 0.0f) atomicAdd(&g_ssum[c], sred[0]);
}

// ---------------------------------------------------------------------------
// Kernel 3 (k_main): unchanged (passing). 256 threads = 8 warps.
// Warp w owns queries 4w..4w+3; lane owns members 2l,2l+1. f32x2 accums.
// ---------------------------------------------------------------------------
__global__ void __launch_bounds__(256)
k_main(const float* __restrict__ xq, const float* __restrict__ xs,
       const int* __restrict__ pos, float* __restrict__ out, float invNq) {
    int b = blockIdx.x;
    if (b >= g_ntiles) return;

    extern __shared__ float4 dsm[];
    float4* s_q4 = dsm;                  // QT rows x 64 float4
    float4* s_m4 = dsm + QT * D4;        // MB rows x 64 float4, XOR-swizzled
    __shared__ float s_lorig[QT];
    __shared__ float s_msn[MB];
    __shared__ int   s_mj[MB];
    __shared__ float s_res[QT];

    int t = threadIdx.x, w = t >> 5, l = t & 31;
    int c    = g_tc[b];
    int qoff = g_toff[b];
    int qcnt = g_tcnt[b];
    float v  = (g_counts[c] > 1) ? -1000.0f : 0.0f;

    float qn[4]; int p[4];
#pragma unroll
    for (int k = 0; k < 4; k++) {
        int ql = 4 * w + k;
        int qi = g_qidx[qoff + min(ql, qcnt - 1)];
        const float4* src = (const float4*)xq + (size_t)qi * D4;
        float4 a = src[l], bb = src[l + 32];
        s_q4[ql * D4 + l]      = a;
        s_q4[ql * D4 + l + 32] = bb;
        float s = a.x*a.x + a.y*a.y + a.z*a.z + a.w*a.w
                + bb.x*bb.x + bb.y*bb.y + bb.z*bb.z + bb.w*bb.w;
        qn[k] = warp_sum(s);
        p[k]  = pos[qi];
    }

    int s0 = g_start[c];
    int Mc = g_start[c + 1] - s0;

    float pm[4], ps[4];
#pragma unroll
    for (int k = 0; k < 4; k++) { pm[k] = NEG; ps[k] = 0.0f; }

    const int m0 = 2 * l, m1 = 2 * l + 1;
    const int sig = l & 7;
    const ulonglong2* mr0 = (const ulonglong2*)(s_m4 + m0 * D4);
    const ulonglong2* mr1 = (const ulonglong2*)(s_m4 + m1 * D4);

    for (int base = 0; base < Mc; base += MB) {
        int nm = min(MB, Mc - base);
        __syncthreads();
        for (int r = 0; r < 8; r++) {
            int m = (r << 3) + w;
            if (m < nm) {
                int j = g_cidx[s0 + base + m];
                int sg = (m >> 1) & 7;
                const float4* src = (const float4*)xs + (size_t)j * D4;
                float4 a = src[l], bb = src[l + 32];
                s_m4[m * D4 + (l ^ sg)]        = a;
                s_m4[m * D4 + ((l + 32) ^ sg)] = bb;
                float s = a.x*a.x + a.y*a.y + a.z*a.z + a.w*a.w
                        + bb.x*bb.x + bb.y*bb.y + bb.z*bb.z + bb.w*bb.w;
                s = warp_sum(s);
                if (l == 0) { s_mj[m] = j; s_msn[m] = s; }
            } else if (l == 0) s_mj[m] = -1;
        }
        __syncthreads();

        unsigned long long acc[4][2];
#pragma unroll
        for (int k = 0; k < 4; k++) { acc[k][0] = 0ull; acc[k][1] = 0ull; }

#pragma unroll 4
        for (int d = 0; d < D4; d++) {
            int cc = d ^ sig;
            ulonglong2 A = mr0[cc];
            ulonglong2 B = mr1[cc];
#pragma unroll
            for (int k = 0; k < 4; k++) {
                ulonglong2 Q = ((const ulonglong2*)(s_q4 + (4 * w + k) * D4))[d];
                fma2(acc[k][0], Q.x, A.x);
                fma2(acc[k][0], Q.y, A.y);
                fma2(acc[k][1], Q.x, B.x);
                fma2(acc[k][1], Q.y, B.y);
            }
        }

        int   j0 = s_mj[m0],  j1 = s_mj[m1];
        float sn0 = s_msn[m0], sn1 = s_msn[m1];
#pragma unroll
        for (int k = 0; k < 4; k++) {
            float d0 = hsum2(acc[k][0]);
            float d1 = hsum2(acc[k][1]);
            float r0 = -0.5f * fmaxf(qn[k] + sn0 - 2.0f * d0, 0.0f);
            float r1 = -0.5f * fmaxf(qn[k] + sn1 - 2.0f * d1, 0.0f);
            float l0 = (j0 < 0) ? NEG : ((j0 == p[k]) ? v : r0);
            float l1 = (j1 < 0) ? NEG : ((j1 == p[k]) ? v : r1);
            if (j0 >= 0 && j0 == p[k]) s_lorig[4 * w + k] = r0;
            if (j1 >= 0 && j1 == p[k]) s_lorig[4 * w + k] = r1;
            float mx = fmaxf(pm[k], fmaxf(l0, l1));
            if (mx > -1e37f) {
                ps[k] = ps[k] * __expf(pm[k] - mx) + __expf(l0 - mx) + __expf(l1 - mx);
                pm[k] = mx;
            }
        }
    }

    float posl[4];
#pragma unroll
    for (int k = 0; k < 4; k++) {
        float m = pm[k], s = ps[k];
        for (int o = 16; o; o >>= 1) {
            float om = __shfl_xor_sync(0xffffffffu, m, o);
            float os = __shfl_xor_sync(0xffffffffu, s, o);
            float mx = fmaxf(m, om);
            if (mx > -1e37f) s = s * __expf(m - mx) + os * __expf(om - mx);
            m = mx;
        }
        posl[k] = m + __logf(s);
    }

    __syncthreads();
    for (int r = 0; r < 8; r++) {
        int m = (r << 3) + w;
        int sg = (m >> 1) & 7;
        const float4* src = (const float4*)g_cent + (size_t)m * D4;
        s_m4[m * D4 + (l ^ sg)]        = src[l];
        s_m4[m * D4 + ((l + 32) ^ sg)] = src[l + 32];
    }
    __syncthreads();

    {
        unsigned long long acc[4][2];
#pragma unroll
        for (int k = 0; k < 4; k++) { acc[k][0] = 0ull; acc[k][1] = 0ull; }

#pragma unroll 4
        for (int d = 0; d < D4; d++) {
            int cc = d ^ sig;
            ulonglong2 A = mr0[cc];
            ulonglong2 B = mr1[cc];
#pragma unroll
            for (int k = 0; k < 4; k++) {
                ulonglong2 Q = ((const ulonglong2*)(s_q4 + (4 * w + k) * D4))[d];
                fma2(acc[k][0], Q.x, A.x);
                fma2(acc[k][0], Q.y, A.y);
                fma2(acc[k][1], Q.x, B.x);
                fma2(acc[k][1], Q.y, B.y);
            }
        }

        float cnt0 = (float)g_counts[m0], cnt1 = (float)g_counts[m1];
        float ss0 = g_ssum[m0], ss1 = g_ssum[m1];
        bool  isc0 = (m0 == c), isc1 = (m1 == c);
#pragma unroll
        for (int k = 0; k < 4; k++) {
            float lo = s_lorig[4 * w + k];
            float x0 = -0.5f * (cnt0 * qn[k] + ss0) + hsum2(acc[k][0]);
            float x1 = -0.5f * (cnt1 * qn[k] + ss1) + hsum2(acc[k][1]);
            if (isc0) x0 += v - lo;
            if (isc1) x1 += v - lo;
            x0 /= cnt0 - (isc0 ? 1.0f : 0.0f);
            x1 /= cnt1 - (isc1 ? 1.0f : 0.0f);
            float m = fmaxf(x0, x1);
            float s = __expf(x0 - m) + __expf(x1 - m);
            for (int o = 16; o; o >>= 1) {
                float om = __shfl_xor_sync(0xffffffffu, m, o);
                float os = __shfl_xor_sync(0xffffffffu, s, o);
                float mx = fmaxf(m, om);
                s = s * __expf(m - mx) + os * __expf(om - mx);
                m = mx;
            }
            if (l == 0) {
                float neg = m + __logf(s);
                s_res[4 * w + k] = (4 * w + k < qcnt) ? (neg - posl[k]) * invNq : 0.0f;
            }
        }
    }

    __syncthreads();
    if (w == 0) {
        float a = s_res[l];
        a = warp_sum(a);
        if (l == 0) atomicAdd(out, a);
    }
}

extern "C" void kernel_launch(void* const* d_in, const int* in_sizes, int n_in,
                              void* d_out, int out_size) {
    const float* xq  = (const float*)d_in[0];
    const int*   yq  = (const int*)  d_in[1];
    const float* xs  = (const float*)d_in[2];
    const int*   ys  = (const int*)  d_in[3];
    const int*   pos = (const int*)  d_in[4];
    int Nq = in_sizes[1];
    int Ns = in_sizes[3];

    cudaFuncSetAttribute(k_main, cudaFuncAttributeMaxDynamicSharedMemorySize, SMEM_MAIN);

    kPrep<<<NH, 256>>>(ys, yq, Nq, Ns, (float*)d_out);
    dim3 gc(C, 2, ZC);
    kCent<<<gc, 128>>>(xs);
    k_main<<<MAXTILES, 256, SMEM_MAIN>>>(xq, xs, pos, (float*)d_out, 1.0f / (float)Nq);
}

// round 12
// speedup vs baseline: 1.1489x; 1.1489x over previous
#include <cuda_runtime.h>
#include <math.h>

#define D4    64            // 256 dims = 64 float4
#define C     64
#define MAXNQ 4096
#define MAXNS 8192
#define QT    32            // queries per tile
#define MB    64            // members per staged chunk
#define MAXTILES (MAXNQ/QT + C)   // 192
#define NEG  (-3.0e38f)
#define NH   48             // histogram/scatter CTAs
#define ZC   32             // kCent member splits
#define SMEM_MAIN ((QT*D4 + MB*D4) * 16)   // 96 KB dynamic

// Scratch (device globals; fully rewritten every call -> replay-safe).
__device__ float g_cent[C * 256];
__device__ float g_ssum[C];
__device__ int   g_counts[C];
__device__ int   g_start[C + 1];
__device__ int   g_cidx[MAXNS];
__device__ int   g_qidx[MAXNQ];
__device__ int   g_tc[MAXTILES], g_toff[MAXTILES], g_tcnt[MAXTILES];
__device__ int   g_ntiles;
__device__ int   g_ph[NH][C];     // per-CTA support histograms (plain stores)
__device__ int   g_pqh[NH][C];    // per-CTA query histograms
__device__ int   g_off[C], g_qoff[C];   // scatter cursors (init by kSched)

__device__ __forceinline__ float warp_sum(float v) {
#pragma unroll
    for (int o = 16; o; o >>= 1) v += __shfl_xor_sync(0xffffffffu, v, o);
    return v;
}

// Packed dual-FMA: d.lo += a.lo*b.lo ; d.hi += a.hi*b.hi   (Blackwell f32x2)
__device__ __forceinline__ void fma2(unsigned long long& d,
                                     unsigned long long a, unsigned long long b) {
    asm("fma.rn.f32x2 %0, %1, %2, %0;" : "+l"(d) : "l"(a), "l"(b));
}
__device__ __forceinline__ float hsum2(unsigned long long v) {
    float lo, hi;
    asm("mov.b64 {%0, %1}, %2;" : "=f"(lo), "=f"(hi) : "l"(v));
    return lo + hi;
}

// ---------------------------------------------------------------------------
// Kernel 1 (kHist): 48 CTAs. Per-CTA label-slice histograms -> partials.
// Also zeroes g_cent / g_ssum / d_out.
// ---------------------------------------------------------------------------
__global__ void kHist(const int* __restrict__ ys, const int* __restrict__ yq,
                      int Nq, int Ns, float* __restrict__ out) {
    __shared__ int h[8][C], hq[8][C];
    int tid = threadIdx.x, w = tid >> 5;
    int cta = blockIdx.x;
    for (int i = tid; i < 8 * C; i += 256) { (&h[0][0])[i] = 0; (&hq[0][0])[i] = 0; }
    __syncthreads();
    int s0 = (Ns * cta) / NH, s1 = (Ns * (cta + 1)) / NH;
    for (int j = s0 + tid; j < s1; j += 256) atomicAdd(&h[w][ys[j]], 1);
    int q0 = (Nq * cta) / NH, q1 = (Nq * (cta + 1)) / NH;
    for (int i = q0 + tid; i < q1; i += 256) atomicAdd(&hq[w][yq[i]], 1);
    __syncthreads();
    if (tid < C) {
        int s = 0;
#pragma unroll
        for (int r = 0; r < 8; r++) s += h[r][tid];
        g_ph[cta][tid] = s;
    } else if (tid < 2 * C) {
        int c = tid - C, s = 0;
#pragma unroll
        for (int r = 0; r < 8; r++) s += hq[r][c];
        g_pqh[cta][c] = s;
    }
    for (int i = cta * 256 + tid; i < C * 256; i += NH * 256) g_cent[i] = 0.0f;
    if (cta == 1 && tid < C) g_ssum[tid] = 0.0f;
    if (cta == 2 && tid == 0) out[0] = 0.0f;
}

// ---------------------------------------------------------------------------
// Kernel 2 (kSched): 1 CTA. Reduce partial hists, prefix, tile schedule,
// init scatter cursors.
// ---------------------------------------------------------------------------
__global__ void kSched() {
    __shared__ int cnt[C], qcnt[C];
    int tid = threadIdx.x;
    if (tid < C) {
        int s = 0;
        for (int r = 0; r < NH; r++) s += g_ph[r][tid];
        cnt[tid] = s;
    } else if (tid < 2 * C) {
        int c = tid - C, s = 0;
        for (int r = 0; r < NH; r++) s += g_pqh[r][c];
        qcnt[c] = s;
    }
    __syncthreads();
    if (tid == 0) {
        int acc = 0, qacc = 0, nt = 0;
        for (int c = 0; c < C; c++) {
            g_counts[c] = cnt[c]; g_start[c] = acc; g_off[c] = acc; acc += cnt[c];
            g_qoff[c] = qacc;
            for (int t = 0; t < qcnt[c]; t += QT) {
                g_tc[nt] = c; g_toff[nt] = qacc + t;
                g_tcnt[nt] = min(QT, qcnt[c] - t); nt++;
            }
            qacc += qcnt[c];
        }
        g_start[C] = acc; g_ntiles = nt;
    }
}

// ---------------------------------------------------------------------------
// Kernel 3 (kScatter): 48 CTAs. Global-atomic scatter.
// ---------------------------------------------------------------------------
__global__ void kScatter(const int* __restrict__ ys, const int* __restrict__ yq,
                         int Nq, int Ns) {
    int tid = threadIdx.x, cta = blockIdx.x;
    int s0 = (Ns * cta) / NH, s1 = (Ns * (cta + 1)) / NH;
    for (int j = s0 + tid; j < s1; j += 256)
        g_cidx[atomicAdd(&g_off[ys[j]], 1)] = j;
    int q0 = (Nq * cta) / NH, q1 = (Nq * (cta + 1)) / NH;
    for (int i = q0 + tid; i < q1; i += 256)
        g_qidx[atomicAdd(&g_qoff[yq[i]], 1)] = i;
}

// ---------------------------------------------------------------------------
// Kernel 4 (kCent): partial centroids + partial sq-norm sums. Grid (C,2,ZC).
// ---------------------------------------------------------------------------
__global__ void kCent(const float* __restrict__ xs) {
    int c = blockIdx.x, tid = threadIdx.x;
    int dim = blockIdx.y * 128 + tid;
    int s0 = g_start[c], s1 = g_start[c + 1];
    int Mc = s1 - s0;
    int b0 = s0 + (Mc * (int)blockIdx.z) / ZC;
    int b1 = s0 + (Mc * ((int)blockIdx.z + 1)) / ZC;
    float acc = 0.0f, acc2 = 0.0f;
    int m = b0;
    for (; m + 3 < b1; m += 4) {
        float v0 = xs[(size_t)g_cidx[m]   * 256 + dim];
        float v1 = xs[(size_t)g_cidx[m+1] * 256 + dim];
        float v2 = xs[(size_t)g_cidx[m+2] * 256 + dim];
        float v3 = xs[(size_t)g_cidx[m+3] * 256 + dim];
        acc  += (v0 + v1) + (v2 + v3);
        acc2 += (v0*v0 + v1*v1) + (v2*v2 + v3*v3);
    }
    for (; m < b1; m++) {
        float v = xs[(size_t)g_cidx[m] * 256 + dim];
        acc += v; acc2 += v * v;
    }
    if (b0 < b1) atomicAdd(&g_cent[c * 256 + dim], acc);

    __shared__ float sred[128];
    sred[tid] = acc2; __syncthreads();
    for (int s = 64; s; s >>= 1) { if (tid < s) sred[tid] += sred[tid + s]; __syncthreads(); }
    if (tid == 0 && blockIdx.y == 0 && sred[0] != 0.0f) atomicAdd(&g_ssum[c], sred[0]);
    if (tid == 1 && blockIdx.y == 1 && sred[0] != 0.0f) atomicAdd(&g_ssum[c], sred[0]);
}

// ---------------------------------------------------------------------------
// Kernel 5 (k_main): 256 threads = 8 warps. Warp w owns queries 4w..4w+3;
// lane owns members 2l,2l+1. Member norms computed IN the FMA d-loop
// (n += A*A) — no shuffles in staging; staging is batched LDG->STS.
// ---------------------------------------------------------------------------
__global__ void __launch_bounds__(256, 2)
k_main(const float* __restrict__ xq, const float* __restrict__ xs,
       const int* __restrict__ pos, float* __restrict__ out, float invNq) {
    int b = blockIdx.x;
    if (b >= g_ntiles) return;

    extern __shared__ float4 dsm[];
    float4* s_q4 = dsm;                  // QT rows x 64 float4
    float4* s_m4 = dsm + QT * D4;        // MB rows x 64 float4, XOR-swizzled
    __shared__ float s_lorig[QT];
    __shared__ int   s_mj[MB];
    __shared__ float s_res[QT];

    int t = threadIdx.x, w = t >> 5, l = t & 31;
    int c    = g_tc[b];
    int qoff = g_toff[b];
    int qcnt = g_tcnt[b];
    float v  = (g_counts[c] > 1) ? -1000.0f : 0.0f;

    float qn[4]; int p[4];
#pragma unroll
    for (int k = 0; k < 4; k++) {
        int ql = 4 * w + k;
        int qi = g_qidx[qoff + min(ql, qcnt - 1)];
        const float4* src = (const float4*)xq + (size_t)qi * D4;
        float4 a = src[l], bb = src[l + 32];
        s_q4[ql * D4 + l]      = a;
        s_q4[ql * D4 + l + 32] = bb;
        float s = a.x*a.x + a.y*a.y + a.z*a.z + a.w*a.w
                + bb.x*bb.x + bb.y*bb.y + bb.z*bb.z + bb.w*bb.w;
        qn[k] = warp_sum(s);
        p[k]  = pos[qi];
    }

    int s0 = g_start[c];
    int Mc = g_start[c + 1] - s0;

    float pm[4], ps[4];
#pragma unroll
    for (int k = 0; k < 4; k++) { pm[k] = NEG; ps[k] = 0.0f; }

    const int m0 = 2 * l, m1 = 2 * l + 1;
    const int sig = l & 7;
    const ulonglong2* mr0 = (const ulonglong2*)(s_m4 + m0 * D4);
    const ulonglong2* mr1 = (const ulonglong2*)(s_m4 + m1 * D4);

    // ---- member chunks: positive (in-class) logsumexp ----
    for (int base = 0; base < Mc; base += MB) {
        int nm = min(MB, Mc - base);
        __syncthreads();
        // staging: 2 rows per iteration, 4 LDGs in flight, no shuffles
#pragma unroll
        for (int r = 0; r < 8; r += 2) {
            int ma = (r << 3) + w, mb = ((r + 1) << 3) + w;
            bool va = (ma < nm), vb = (mb < nm);
            int ja = va ? g_cidx[s0 + base + ma] : 0;
            int jb = vb ? g_cidx[s0 + base + mb] : 0;
            const float4* pa = (const float4*)xs + (size_t)ja * D4;
            const float4* pb = (const float4*)xs + (size_t)jb * D4;
            float4 a0 = pa[l], a1 = pa[l + 32];
            float4 b0 = pb[l], b1 = pb[l + 32];
            int sga = (ma >> 1) & 7, sgb = (mb >> 1) & 7;
            if (va) {
                s_m4[ma * D4 + (l ^ sga)]        = a0;
                s_m4[ma * D4 + ((l + 32) ^ sga)] = a1;
            }
            if (vb) {
                s_m4[mb * D4 + (l ^ sgb)]        = b0;
                s_m4[mb * D4 + ((l + 32) ^ sgb)] = b1;
            }
            if (l == 0) { s_mj[ma] = va ? ja : -1; s_mj[mb] = vb ? jb : -1; }
        }
        __syncthreads();

        unsigned long long acc[4][2];
        unsigned long long n0 = 0ull, n1 = 0ull;
#pragma unroll
        for (int k = 0; k < 4; k++) { acc[k][0] = 0ull; acc[k][1] = 0ull; }

#pragma unroll 8
        for (int d = 0; d < D4; d++) {
            int cc = d ^ sig;
            ulonglong2 A = mr0[cc];
            ulonglong2 B = mr1[cc];
            fma2(n0, A.x, A.x); fma2(n0, A.y, A.y);
            fma2(n1, B.x, B.x); fma2(n1, B.y, B.y);
#pragma unroll
            for (int k = 0; k < 4; k++) {
                ulonglong2 Q = ((const ulonglong2*)(s_q4 + (4 * w + k) * D4))[d];
                fma2(acc[k][0], Q.x, A.x);
                fma2(acc[k][0], Q.y, A.y);
                fma2(acc[k][1], Q.x, B.x);
                fma2(acc[k][1], Q.y, B.y);
            }
        }

        int   j0 = s_mj[m0],  j1 = s_mj[m1];
        float sn0 = hsum2(n0), sn1 = hsum2(n1);
#pragma unroll
        for (int k = 0; k < 4; k++) {
            float d0 = hsum2(acc[k][0]);
            float d1 = hsum2(acc[k][1]);
            float r0 = -0.5f * fmaxf(qn[k] + sn0 - 2.0f * d0, 0.0f);
            float r1 = -0.5f * fmaxf(qn[k] + sn1 - 2.0f * d1, 0.0f);
            float l0 = (j0 < 0) ? NEG : ((j0 == p[k]) ? v : r0);
            float l1 = (j1 < 0) ? NEG : ((j1 == p[k]) ? v : r1);
            if (j0 >= 0 && j0 == p[k]) s_lorig[4 * w + k] = r0;
            if (j1 >= 0 && j1 == p[k]) s_lorig[4 * w + k] = r1;
            float mx = fmaxf(pm[k], fmaxf(l0, l1));
            if (mx > -1e37f) {
                ps[k] = ps[k] * __expf(pm[k] - mx) + __expf(l0 - mx) + __expf(l1 - mx);
                pm[k] = mx;
            }
        }
    }

    // warp-reduce positive logsumexp
    float posl[4];
#pragma unroll
    for (int k = 0; k < 4; k++) {
        float m = pm[k], s = ps[k];
        for (int o = 16; o; o >>= 1) {
            float om = __shfl_xor_sync(0xffffffffu, m, o);
            float os = __shfl_xor_sync(0xffffffffu, s, o);
            float mx = fmaxf(m, om);
            if (mx > -1e37f) s = s * __expf(m - mx) + os * __expf(om - mx);
            m = mx;
        }
        posl[k] = m + __logf(s);
    }

    // ---- centroid chunk: negative term (closed form + diagonal correction) ----
    __syncthreads();
#pragma unroll
    for (int r = 0; r < 8; r++) {
        int m = (r << 3) + w;
        int sg = (m >> 1) & 7;
        const float4* src = (const float4*)g_cent + (size_t)m * D4;
        s_m4[m * D4 + (l ^ sg)]        = src[l];
        s_m4[m * D4 + ((l + 32) ^ sg)] = src[l + 32];
    }
    __syncthreads();

    {
        unsigned long long acc[4][2];
#pragma unroll
        for (int k = 0; k < 4; k++) { acc[k][0] = 0ull; acc[k][1] = 0ull; }

#pragma unroll 8
        for (int d = 0; d < D4; d++) {
            int cc = d ^ sig;
            ulonglong2 A = mr0[cc];
            ulonglong2 B = mr1[cc];
#pragma unroll
            for (int k = 0; k < 4; k++) {
                ulonglong2 Q = ((const ulonglong2*)(s_q4 + (4 * w + k) * D4))[d];
                fma2(acc[k][0], Q.x, A.x);
                fma2(acc[k][0], Q.y, A.y);
                fma2(acc[k][1], Q.x, B.x);
                fma2(acc[k][1], Q.y, B.y);
            }
        }

        float cnt0 = (float)g_counts[m0], cnt1 = (float)g_counts[m1];
        float ss0 = g_ssum[m0], ss1 = g_ssum[m1];
        bool  isc0 = (m0 == c), isc1 = (m1 == c);
#pragma unroll
        for (int k = 0; k < 4; k++) {
            float lo = s_lorig[4 * w + k];
            float x0 = -0.5f * (cnt0 * qn[k] + ss0) + hsum2(acc[k][0]);
            float x1 = -0.5f * (cnt1 * qn[k] + ss1) + hsum2(acc[k][1]);
            if (isc0) x0 += v - lo;
            if (isc1) x1 += v - lo;
            x0 /= cnt0 - (isc0 ? 1.0f : 0.0f);
            x1 /= cnt1 - (isc1 ? 1.0f : 0.0f);
            float m = fmaxf(x0, x1);
            float s = __expf(x0 - m) + __expf(x1 - m);
            for (int o = 16; o; o >>= 1) {
                float om = __shfl_xor_sync(0xffffffffu, m, o);
                float os = __shfl_xor_sync(0xffffffffu, s, o);
                float mx = fmaxf(m, om);
                s = s * __expf(m - mx) + os * __expf(om - mx);
                m = mx;
            }
            if (l == 0) {
                float neg = m + __logf(s);
                s_res[4 * w + k] = (4 * w + k < qcnt) ? (neg - posl[k]) * invNq : 0.0f;
            }
        }
    }

    __syncthreads();
    if (w == 0) {
        float a = s_res[l];
        a = warp_sum(a);
        if (l == 0) atomicAdd(out, a);
    }
}

extern "C" void kernel_launch(void* const* d_in, const int* in_sizes, int n_in,
                              void* d_out, int out_size) {
    const float* xq  = (const float*)d_in[0];
    const int*   yq  = (const int*)  d_in[1];
    const float* xs  = (const float*)d_in[2];
    const int*   ys  = (const int*)  d_in[3];
    const int*   pos = (const int*)  d_in[4];
    int Nq = in_sizes[1];
    int Ns = in_sizes[3];

    cudaFuncSetAttribute(k_main, cudaFuncAttributeMaxDynamicSharedMemorySize, SMEM_MAIN);

    kHist<<<NH, 256>>>(ys, yq, Nq, Ns, (float*)d_out);
    kSched<<<1, 256>>>();
    kScatter<<<NH, 256>>>(ys, yq, Nq, Ns);
    dim3 gc(C, 2, ZC);
    kCent<<<gc, 128>>>(xs);
    k_main<<<MAXTILES, 256, SMEM_MAIN>>>(xq, xs, pos, (float*)d_out, 1.0f / (float)Nq);
}

// round 13
// speedup vs baseline: 1.2081x; 1.0515x over previous
#include <cuda_runtime.h>
#include <math.h>

#define D4    64            // 256 dims = 64 float4
#define C     64
#define MAXNQ 4096
#define MAXNS 8192
#define QT    32            // queries per tile
#define MB    64            // members per staged chunk
#define MAXTILES (MAXNQ/QT + C)   // 192
#define NEG  (-3.0e38f)
#define NH   48             // histogram/scatter CTAs
#define ZC   16             // kCent member splits
#define SMEM_MAIN ((QT*D4 + MB*D4) * 16)   // 96 KB dynamic

// Scratch (device globals; fully rewritten every call -> replay-safe).
__device__ float g_cent[C * 256];
__device__ float g_ssum[C];
__device__ int   g_counts[C];
__device__ int   g_start[C + 1];
__device__ int   g_cidx[MAXNS];
__device__ int   g_qidx[MAXNQ];
__device__ int   g_tc[MAXTILES], g_toff[MAXTILES], g_tcnt[MAXTILES];
__device__ int   g_ntiles;
__device__ int   g_ph[NH][C];     // per-CTA support histograms (plain stores)
__device__ int   g_pqh[NH][C];    // per-CTA query histograms

__device__ __forceinline__ float warp_sum(float v) {
#pragma unroll
    for (int o = 16; o; o >>= 1) v += __shfl_xor_sync(0xffffffffu, v, o);
    return v;
}

// Packed dual-FMA: d.lo += a.lo*b.lo ; d.hi += a.hi*b.hi   (Blackwell f32x2)
__device__ __forceinline__ void fma2(unsigned long long& d,
                                     unsigned long long a, unsigned long long b) {
    asm("fma.rn.f32x2 %0, %1, %2, %0;" : "+l"(d) : "l"(a), "l"(b));
}
__device__ __forceinline__ float hsum2(unsigned long long v) {
    float lo, hi;
    asm("mov.b64 {%0, %1}, %2;" : "=f"(lo), "=f"(hi) : "l"(v));
    return lo + hi;
}

// ---------------------------------------------------------------------------
// Kernel 1 (kHist): 48 CTAs. Per-CTA label-slice histograms -> partials.
// Also zeroes g_cent / g_ssum / d_out.
// ---------------------------------------------------------------------------
__global__ void kHist(const int* __restrict__ ys, const int* __restrict__ yq,
                      int Nq, int Ns, float* __restrict__ out) {
    __shared__ int h[8][C], hq[8][C];
    int tid = threadIdx.x, w = tid >> 5;
    int cta = blockIdx.x;
    for (int i = tid; i < 8 * C; i += 256) { (&h[0][0])[i] = 0; (&hq[0][0])[i] = 0; }
    __syncthreads();
    int s0 = (Ns * cta) / NH, s1 = (Ns * (cta + 1)) / NH;
    for (int j = s0 + tid; j < s1; j += 256) atomicAdd(&h[w][ys[j]], 1);
    int q0 = (Nq * cta) / NH, q1 = (Nq * (cta + 1)) / NH;
    for (int i = q0 + tid; i < q1; i += 256) atomicAdd(&hq[w][yq[i]], 1);
    __syncthreads();
    if (tid < C) {
        int s = 0;
#pragma unroll
        for (int r = 0; r < 8; r++) s += h[r][tid];
        g_ph[cta][tid] = s;
    } else if (tid < 2 * C) {
        int c = tid - C, s = 0;
#pragma unroll
        for (int r = 0; r < 8; r++) s += hq[r][c];
        g_pqh[cta][c] = s;
    }
    for (int i = cta * 256 + tid; i < C * 256; i += NH * 256) g_cent[i] = 0.0f;
    if (cta == 1 && tid < C) g_ssum[tid] = 0.0f;
    if (cta == 2 && tid == 0) out[0] = 0.0f;
}

// ---------------------------------------------------------------------------
// Kernel 2 (kScatSched): 48 CTAs. Each CTA derives its own deterministic
// scatter bases from the partial-hist table (no global cursors, no kSched
// launch). CTA 0 additionally writes g_counts / g_start and the schedule.
// ---------------------------------------------------------------------------
__global__ void __launch_bounds__(256)
kScatSched(const int* __restrict__ ys, const int* __restrict__ yq,
           int Nq, int Ns) {
    __shared__ int cnt[C], pre[C], qcnt[C], qpre[C];
    __shared__ int start[C], qstart[C];
    __shared__ int sbase[C], qsbase[C];
    int tid = threadIdx.x, cta = blockIdx.x;

    if (tid < C) {
        int c = tid, s = 0, p = 0;
#pragma unroll 8
        for (int r = 0; r < NH; r++) {
            int v = g_ph[r][c];
            s += v;
            if (r < cta) p += v;
        }
        cnt[c] = s; pre[c] = p;
    } else if (tid < 2 * C) {
        int c = tid - C, s = 0, p = 0;
#pragma unroll 8
        for (int r = 0; r < NH; r++) {
            int v = g_pqh[r][c];
            s += v;
            if (r < cta) p += v;
        }
        qcnt[c] = s; qpre[c] = p;
    }
    __syncthreads();
    if (tid == 0) {
        int acc = 0;
        for (int c = 0; c < C; c++) { start[c] = acc; acc += cnt[c]; }
        if (cta == 0) g_start[C] = acc;
    } else if (tid == 32) {
        int acc = 0;
        for (int c = 0; c < C; c++) { qstart[c] = acc; acc += qcnt[c]; }
    }
    __syncthreads();
    if (tid < C) {
        sbase[tid]  = start[tid]  + pre[tid];
        qsbase[tid] = qstart[tid] + qpre[tid];
        if (cta == 0) { g_counts[tid] = cnt[tid]; g_start[tid] = start[tid]; }
    }
    if (cta == 0 && tid == 64) {
        // build tile schedule (serial, tiny)
        int nt = 0;
        for (int c = 0; c < C; c++) {
            for (int t2 = 0; t2 < qcnt[c]; t2 += QT) {
                g_tc[nt] = c; g_toff[nt] = qstart[c] + t2;
                g_tcnt[nt] = min(QT, qcnt[c] - t2); nt++;
            }
        }
        g_ntiles = nt;
    }
    __syncthreads();

    int s0 = (Ns * cta) / NH, s1 = (Ns * (cta + 1)) / NH;
    for (int j = s0 + tid; j < s1; j += 256)
        g_cidx[atomicAdd(&sbase[ys[j]], 1)] = j;
    int q0 = (Nq * cta) / NH, q1 = (Nq * (cta + 1)) / NH;
    for (int i = q0 + tid; i < q1; i += 256)
        g_qidx[atomicAdd(&qsbase[yq[i]], 1)] = i;
}

// ---------------------------------------------------------------------------
// Kernel 3 (kCent): partial centroids + sq-norm sums, float4 loads.
// Grid (C, ZC), 128 threads: lane f owns float4 f, group g owns rows g,g+2,...
// ---------------------------------------------------------------------------
__global__ void kCent(const float* __restrict__ xs) {
    int c = blockIdx.x, z = blockIdx.y;
    int t = threadIdx.x;
    int f = t & 63;         // float4 index within row
    int g = t >> 6;         // row group 0/1
    int s0 = g_start[c], s1 = g_start[c + 1];
    int Mc = s1 - s0;
    int b0 = s0 + (Mc * z) / ZC;
    int b1 = s0 + (Mc * (z + 1)) / ZC;

    float4 acc = make_float4(0.f, 0.f, 0.f, 0.f);
    float acc2 = 0.0f;
    int m = b0 + g;
    for (; m + 2 < b1; m += 4) {
        int j0 = g_cidx[m], j1 = g_cidx[m + 2];
        float4 v0 = ((const float4*)xs)[(size_t)j0 * D4 + f];
        float4 v1 = ((const float4*)xs)[(size_t)j1 * D4 + f];
        acc.x += v0.x + v1.x; acc.y += v0.y + v1.y;
        acc.z += v0.z + v1.z; acc.w += v0.w + v1.w;
        acc2 += v0.x*v0.x + v0.y*v0.y + v0.z*v0.z + v0.w*v0.w
              + v1.x*v1.x + v1.y*v1.y + v1.z*v1.z + v1.w*v1.w;
    }
    for (; m < b1; m += 2) {
        int j = g_cidx[m];
        float4 v = ((const float4*)xs)[(size_t)j * D4 + f];
        acc.x += v.x; acc.y += v.y; acc.z += v.z; acc.w += v.w;
        acc2 += v.x*v.x + v.y*v.y + v.z*v.z + v.w*v.w;
    }

    if (acc2 != 0.0f) {
        float* dst = &g_cent[c * 256 + f * 4];
        atomicAdd(dst + 0, acc.x); atomicAdd(dst + 1, acc.y);
        atomicAdd(dst + 2, acc.z); atomicAdd(dst + 3, acc.w);
    }

    __shared__ float sred[128];
    sred[t] = acc2; __syncthreads();
    for (int s = 64; s; s >>= 1) { if (t < s) sred[t] += sred[t + s]; __syncthreads(); }
    if (t == 0 && sred[0] != 0.0f) atomicAdd(&g_ssum[c], sred[0]);
}

// ---------------------------------------------------------------------------
// Kernel 4 (k_main): unchanged from R12 (passing). 256 threads = 8 warps.
// ---------------------------------------------------------------------------
__global__ void __launch_bounds__(256, 2)
k_main(const float* __restrict__ xq, const float* __restrict__ xs,
       const int* __restrict__ pos, float* __restrict__ out, float invNq) {
    int b = blockIdx.x;
    if (b >= g_ntiles) return;

    extern __shared__ float4 dsm[];
    float4* s_q4 = dsm;                  // QT rows x 64 float4
    float4* s_m4 = dsm + QT * D4;        // MB rows x 64 float4, XOR-swizzled
    __shared__ float s_lorig[QT];
    __shared__ int   s_mj[MB];
    __shared__ float s_res[QT];

    int t = threadIdx.x, w = t >> 5, l = t & 31;
    int c    = g_tc[b];
    int qoff = g_toff[b];
    int qcnt = g_tcnt[b];
    float v  = (g_counts[c] > 1) ? -1000.0f : 0.0f;

    float qn[4]; int p[4];
#pragma unroll
    for (int k = 0; k < 4; k++) {
        int ql = 4 * w + k;
        int qi = g_qidx[qoff + min(ql, qcnt - 1)];
        const float4* src = (const float4*)xq + (size_t)qi * D4;
        float4 a = src[l], bb = src[l + 32];
        s_q4[ql * D4 + l]      = a;
        s_q4[ql * D4 + l + 32] = bb;
        float s = a.x*a.x + a.y*a.y + a.z*a.z + a.w*a.w
                + bb.x*bb.x + bb.y*bb.y + bb.z*bb.z + bb.w*bb.w;
        qn[k] = warp_sum(s);
        p[k]  = pos[qi];
    }

    int s0 = g_start[c];
    int Mc = g_start[c + 1] - s0;

    float pm[4], ps[4];
#pragma unroll
    for (int k = 0; k < 4; k++) { pm[k] = NEG; ps[k] = 0.0f; }

    const int m0 = 2 * l, m1 = 2 * l + 1;
    const int sig = l & 7;
    const ulonglong2* mr0 = (const ulonglong2*)(s_m4 + m0 * D4);
    const ulonglong2* mr1 = (const ulonglong2*)(s_m4 + m1 * D4);

    for (int base = 0; base < Mc; base += MB) {
        int nm = min(MB, Mc - base);
        __syncthreads();
#pragma unroll
        for (int r = 0; r < 8; r += 2) {
            int ma = (r << 3) + w, mb = ((r + 1) << 3) + w;
            bool va = (ma < nm), vb = (mb < nm);
            int ja = va ? g_cidx[s0 + base + ma] : 0;
            int jb = vb ? g_cidx[s0 + base + mb] : 0;
            const float4* pa = (const float4*)xs + (size_t)ja * D4;
            const float4* pb = (const float4*)xs + (size_t)jb * D4;
            float4 a0 = pa[l], a1 = pa[l + 32];
            float4 b0 = pb[l], b1 = pb[l + 32];
            int sga = (ma >> 1) & 7, sgb = (mb >> 1) & 7;
            if (va) {
                s_m4[ma * D4 + (l ^ sga)]        = a0;
                s_m4[ma * D4 + ((l + 32) ^ sga)] = a1;
            }
            if (vb) {
                s_m4[mb * D4 + (l ^ sgb)]        = b0;
                s_m4[mb * D4 + ((l + 32) ^ sgb)] = b1;
            }
            if (l == 0) { s_mj[ma] = va ? ja : -1; s_mj[mb] = vb ? jb : -1; }
        }
        __syncthreads();

        unsigned long long acc[4][2];
        unsigned long long n0 = 0ull, n1 = 0ull;
#pragma unroll
        for (int k = 0; k < 4; k++) { acc[k][0] = 0ull; acc[k][1] = 0ull; }

#pragma unroll 8
        for (int d = 0; d < D4; d++) {
            int cc = d ^ sig;
            ulonglong2 A = mr0[cc];
            ulonglong2 B = mr1[cc];
            fma2(n0, A.x, A.x); fma2(n0, A.y, A.y);
            fma2(n1, B.x, B.x); fma2(n1, B.y, B.y);
#pragma unroll
            for (int k = 0; k < 4; k++) {
                ulonglong2 Q = ((const ulonglong2*)(s_q4 + (4 * w + k) * D4))[d];
                fma2(acc[k][0], Q.x, A.x);
                fma2(acc[k][0], Q.y, A.y);
                fma2(acc[k][1], Q.x, B.x);
                fma2(acc[k][1], Q.y, B.y);
            }
        }

        int   j0 = s_mj[m0],  j1 = s_mj[m1];
        float sn0 = hsum2(n0), sn1 = hsum2(n1);
#pragma unroll
        for (int k = 0; k < 4; k++) {
            float d0 = hsum2(acc[k][0]);
            float d1 = hsum2(acc[k][1]);
            float r0 = -0.5f * fmaxf(qn[k] + sn0 - 2.0f * d0, 0.0f);
            float r1 = -0.5f * fmaxf(qn[k] + sn1 - 2.0f * d1, 0.0f);
            float l0 = (j0 < 0) ? NEG : ((j0 == p[k]) ? v : r0);
            float l1 = (j1 < 0) ? NEG : ((j1 == p[k]) ? v : r1);
            if (j0 >= 0 && j0 == p[k]) s_lorig[4 * w + k] = r0;
            if (j1 >= 0 && j1 == p[k]) s_lorig[4 * w + k] = r1;
            float mx = fmaxf(pm[k], fmaxf(l0, l1));
            if (mx > -1e37f) {
                ps[k] = ps[k] * __expf(pm[k] - mx) + __expf(l0 - mx) + __expf(l1 - mx);
                pm[k] = mx;
            }
        }
    }

    float posl[4];
#pragma unroll
    for (int k = 0; k < 4; k++) {
        float m = pm[k], s = ps[k];
        for (int o = 16; o; o >>= 1) {
            float om = __shfl_xor_sync(0xffffffffu, m, o);
            float os = __shfl_xor_sync(0xffffffffu, s, o);
            float mx = fmaxf(m, om);
            if (mx > -1e37f) s = s * __expf(m - mx) + os * __expf(om - mx);
            m = mx;
        }
        posl[k] = m + __logf(s);
    }

    __syncthreads();
#pragma unroll
    for (int r = 0; r < 8; r++) {
        int m = (r << 3) + w;
        int sg = (m >> 1) & 7;
        const float4* src = (const float4*)g_cent + (size_t)m * D4;
        s_m4[m * D4 + (l ^ sg)]        = src[l];
        s_m4[m * D4 + ((l + 32) ^ sg)] = src[l + 32];
    }
    __syncthreads();

    {
        unsigned long long acc[4][2];
#pragma unroll
        for (int k = 0; k < 4; k++) { acc[k][0] = 0ull; acc[k][1] = 0ull; }

#pragma unroll 8
        for (int d = 0; d < D4; d++) {
            int cc = d ^ sig;
            ulonglong2 A = mr0[cc];
            ulonglong2 B = mr1[cc];
#pragma unroll
            for (int k = 0; k < 4; k++) {
                ulonglong2 Q = ((const ulonglong2*)(s_q4 + (4 * w + k) * D4))[d];
                fma2(acc[k][0], Q.x, A.x);
                fma2(acc[k][0], Q.y, A.y);
                fma2(acc[k][1], Q.x, B.x);
                fma2(acc[k][1], Q.y, B.y);
            }
        }

        float cnt0 = (float)g_counts[m0], cnt1 = (float)g_counts[m1];
        float ss0 = g_ssum[m0], ss1 = g_ssum[m1];
        bool  isc0 = (m0 == c), isc1 = (m1 == c);
#pragma unroll
        for (int k = 0; k < 4; k++) {
            float lo = s_lorig[4 * w + k];
            float x0 = -0.5f * (cnt0 * qn[k] + ss0) + hsum2(acc[k][0]);
            float x1 = -0.5f * (cnt1 * qn[k] + ss1) + hsum2(acc[k][1]);
            if (isc0) x0 += v - lo;
            if (isc1) x1 += v - lo;
            x0 /= cnt0 - (isc0 ? 1.0f : 0.0f);
            x1 /= cnt1 - (isc1 ? 1.0f : 0.0f);
            float m = fmaxf(x0, x1);
            float s = __expf(x0 - m) + __expf(x1 - m);
            for (int o = 16; o; o >>= 1) {
                float om = __shfl_xor_sync(0xffffffffu, m, o);
                float os = __shfl_xor_sync(0xffffffffu, s, o);
                float mx = fmaxf(m, om);
                s = s * __expf(m - mx) + os * __expf(om - mx);
                m = mx;
            }
            if (l == 0) {
                float neg = m + __logf(s);
                s_res[4 * w + k] = (4 * w + k < qcnt) ? (neg - posl[k]) * invNq : 0.0f;
            }
        }
    }

    __syncthreads();
    if (w == 0) {
        float a = s_res[l];
        a = warp_sum(a);
        if (l == 0) atomicAdd(out, a);
    }
}

extern "C" void kernel_launch(void* const* d_in, const int* in_sizes, int n_in,
                              void* d_out, int out_size) {
    const float* xq  = (const float*)d_in[0];
    const int*   yq  = (const int*)  d_in[1];
    const float* xs  = (const float*)d_in[2];
    const int*   ys  = (const int*)  d_in[3];
    const int*   pos = (const int*)  d_in[4];
    int Nq = in_sizes[1];
    int Ns = in_sizes[3];

    cudaFuncSetAttribute(k_main, cudaFuncAttributeMaxDynamicSharedMemorySize, SMEM_MAIN);

    kHist<<<NH, 256>>>(ys, yq, Nq, Ns, (float*)d_out);
    kScatSched<<<NH, 256>>>(ys, yq, Nq, Ns);
    dim3 gc(C, ZC);
    kCent<<<gc, 128>>>(xs);
    k_main<<<MAXTILES, 256, SMEM_MAIN>>>(xq, xs, pos, (float*)d_out, 1.0f / (float)Nq);
}